// round 1
// baseline (speedup 1.0000x reference)
#include <cuda_runtime.h>
#include <cuda_bf16.h>
#include <math.h>
#include <stdint.h>

// ---------------------------------------------------------------------------
// MiniGPT4AttentionCam: B=1, S=4096, HID=2048, 16 heads x 128
// CAM mask: keys [0,410) U [3072,4096)  (non-causal, query-independent)
// Pipeline: QKV proj (TF32 mma) -> RoPE(Q in-place) -> RoPE+compact K,
//           compact V -> flash attention over 1536-padded compact keys
//           (TF32 mma) -> O proj (TF32 mma).
// ---------------------------------------------------------------------------

#define SEQ    4096
#define HID    2048
#define HEADS  16
#define HD     128
#define SB     410          // start budget = ceil(0.1*4096)
#define RSTART 3072         // SEQ - recent_budget(1024)
#define KC     1434         // compact key count
#define KCP    1536         // padded to 12 * 128
#define NKT    12           // key tiles

// Scratch (device globals: sanctioned alloc-free workaround)
__device__ float g_q [(size_t)SEQ * HID];
__device__ float g_k [(size_t)SEQ * HID];
__device__ float g_v [(size_t)SEQ * HID];
__device__ float g_kc[(size_t)HEADS * KCP * HD];
__device__ float g_vc[(size_t)HEADS * KCP * HD];
__device__ float g_ao[(size_t)SEQ * HID];
__device__ float g_theta[64];

__device__ __forceinline__ float f2tf(float x) {
    uint32_t r;
    asm("cvt.rna.tf32.f32 %0, %1;" : "=r"(r) : "f"(x));
    return __uint_as_float(r);
}

__device__ __forceinline__ void mma_tf32(float c[4],
    uint32_t a0, uint32_t a1, uint32_t a2, uint32_t a3,
    uint32_t b0, uint32_t b1)
{
    asm volatile(
        "mma.sync.aligned.m16n8k8.row.col.f32.tf32.tf32.f32 "
        "{%0,%1,%2,%3}, {%4,%5,%6,%7}, {%8,%9}, {%0,%1,%2,%3};\n"
        : "+f"(c[0]), "+f"(c[1]), "+f"(c[2]), "+f"(c[3])
        : "r"(a0), "r"(a1), "r"(a2), "r"(a3), "r"(b0), "r"(b1));
}

// ---------------------------------------------------------------------------
// C[M,N] = A[M,K] @ B[N,K]^T + bias   (TN layout, TF32, fp32 accumulate)
// Block 128x128, BK=32, 256 threads, 8 warps (4m x 2n), warp tile 32x64.
// ---------------------------------------------------------------------------
__global__ __launch_bounds__(256)
void gemm_tn(const float* __restrict__ A, const float* __restrict__ B,
             const float* __restrict__ bias, float* __restrict__ C,
             int M, int N, int K)
{
    __shared__ float sA[128][40];   // pad 40 -> float4-aligned, conflict-free frags
    __shared__ float sB[128][40];

    const int tid  = threadIdx.x;
    const int w    = tid >> 5, lane = tid & 31;
    const int g    = lane >> 2, tg = lane & 3;
    const int wm   = w & 3,  wn = w >> 2;
    const int m0   = blockIdx.y * 128, n0 = blockIdx.x * 128;

    float acc[2][8][4];
    #pragma unroll
    for (int a = 0; a < 2; a++)
        #pragma unroll
        for (int b = 0; b < 8; b++)
            #pragma unroll
            for (int q = 0; q < 4; q++) acc[a][b][q] = 0.f;

    for (int k0 = 0; k0 < K; k0 += 32) {
        #pragma unroll
        for (int i = 0; i < 4; i++) {
            int idx = tid + i * 256;
            int r = idx >> 3, c = (idx & 7) << 2;
            float4 va = *(const float4*)(A + (size_t)(m0 + r) * K + k0 + c);
            sA[r][c + 0] = f2tf(va.x); sA[r][c + 1] = f2tf(va.y);
            sA[r][c + 2] = f2tf(va.z); sA[r][c + 3] = f2tf(va.w);
            float4 vb = *(const float4*)(B + (size_t)(n0 + r) * K + k0 + c);
            sB[r][c + 0] = f2tf(vb.x); sB[r][c + 1] = f2tf(vb.y);
            sB[r][c + 2] = f2tf(vb.z); sB[r][c + 3] = f2tf(vb.w);
        }
        __syncthreads();

        #pragma unroll
        for (int ks = 0; ks < 4; ks++) {
            const int kk = ks << 3;
            uint32_t af[2][4], bf[8][2];
            #pragma unroll
            for (int mt = 0; mt < 2; mt++) {
                int rb = wm * 32 + mt * 16;
                af[mt][0] = __float_as_uint(sA[rb + g    ][kk + tg    ]);
                af[mt][1] = __float_as_uint(sA[rb + g + 8][kk + tg    ]);
                af[mt][2] = __float_as_uint(sA[rb + g    ][kk + tg + 4]);
                af[mt][3] = __float_as_uint(sA[rb + g + 8][kk + tg + 4]);
            }
            #pragma unroll
            for (int nt = 0; nt < 8; nt++) {
                int nb = wn * 64 + nt * 8;
                bf[nt][0] = __float_as_uint(sB[nb + g][kk + tg    ]);
                bf[nt][1] = __float_as_uint(sB[nb + g][kk + tg + 4]);
            }
            #pragma unroll
            for (int mt = 0; mt < 2; mt++)
                #pragma unroll
                for (int nt = 0; nt < 8; nt++)
                    mma_tf32(acc[mt][nt], af[mt][0], af[mt][1], af[mt][2], af[mt][3],
                             bf[nt][0], bf[nt][1]);
        }
        __syncthreads();
    }

    #pragma unroll
    for (int mt = 0; mt < 2; mt++) {
        int r0 = m0 + wm * 32 + mt * 16 + g;
        #pragma unroll
        for (int nt = 0; nt < 8; nt++) {
            int cc = n0 + wn * 64 + nt * 8 + tg * 2;
            float2 b2 = *(const float2*)(bias + cc);
            float2 s0 = make_float2(acc[mt][nt][0] + b2.x, acc[mt][nt][1] + b2.y);
            float2 s1 = make_float2(acc[mt][nt][2] + b2.x, acc[mt][nt][3] + b2.y);
            *(float2*)(C + (size_t)r0 * N + cc)       = s0;
            *(float2*)(C + (size_t)(r0 + 8) * N + cc) = s1;
        }
    }
}

// ---------------------------------------------------------------------------
// RoPE tables + prep kernels
// ---------------------------------------------------------------------------
__global__ void theta_kernel() {
    int p = threadIdx.x;
    if (p < 64) g_theta[p] = (float)pow(10000.0, -(double)p / 64.0);
}

// RoPE Q in-place (+ fold softmax scale, round to tf32). One warp per (s,h) row.
__global__ void rope_q_kernel() {
    int gw   = (blockIdx.x * blockDim.x + threadIdx.x) >> 5;
    int lane = threadIdx.x & 31;
    if (gw >= SEQ * HEADS) return;
    int s = gw >> 4;
    int h = gw & (HEADS - 1);
    const float scale = 0.08838834764831845f;   // 1/sqrt(128)
    float* row = g_q + (size_t)s * HID + h * HD;

    float x1[2], x2[2], o1[2], o2[2];
    #pragma unroll
    for (int pp = 0; pp < 2; pp++) {
        int p = lane + pp * 32;
        x1[pp] = row[2 * p];
        x2[pp] = row[2 * p + 1];
    }
    __syncwarp();
    #pragma unroll
    for (int pp = 0; pp < 2; pp++) {
        int p = lane + pp * 32;
        float ang = (float)s * g_theta[p];
        float sn = sinf(ang), cs = cosf(ang);
        o1[pp] = f2tf((x1[pp] * cs - x2[pp] * sn) * scale);
        o2[pp] = f2tf((x1[pp] * sn + x2[pp] * cs) * scale);
    }
    #pragma unroll
    for (int pp = 0; pp < 2; pp++) {
        int p = lane + pp * 32;
        row[p]      = o1[pp];
        row[p + 64] = o2[pp];
    }
}

// RoPE K + gather into compact layout g_kc[h][j][d] (zero-pad j>=KC).
__global__ void rope_kc_kernel() {
    int gw   = (blockIdx.x * blockDim.x + threadIdx.x) >> 5;
    int lane = threadIdx.x & 31;
    if (gw >= HEADS * KCP) return;
    int h = gw / KCP;
    int j = gw % KCP;
    float* dst = g_kc + ((size_t)h * KCP + j) * HD;
    if (j >= KC) {
        #pragma unroll
        for (int i = 0; i < 4; i++) dst[lane + 32 * i] = 0.f;
        return;
    }
    int s = (j < SB) ? j : (RSTART + (j - SB));
    const float* src = g_k + (size_t)s * HID + h * HD;
    #pragma unroll
    for (int pp = 0; pp < 2; pp++) {
        int p = lane + pp * 32;
        float x1 = src[2 * p], x2 = src[2 * p + 1];
        float ang = (float)s * g_theta[p];
        float sn = sinf(ang), cs = cosf(ang);
        dst[p]      = f2tf(x1 * cs - x2 * sn);
        dst[p + 64] = f2tf(x1 * sn + x2 * cs);
    }
}

// Gather V into compact layout g_vc[h][j][d] (zero-pad).
__global__ void copy_vc_kernel() {
    int idx = blockIdx.x * blockDim.x + threadIdx.x;   // float4 granularity
    if (idx >= HEADS * KCP * 32) return;
    int c4  = (idx & 31) * 4;
    int row = idx >> 5;
    int h = row / KCP, j = row % KCP;
    float4 v = make_float4(0.f, 0.f, 0.f, 0.f);
    if (j < KC) {
        int s = (j < SB) ? j : (RSTART + (j - SB));
        v = *(const float4*)(g_v + (size_t)s * HID + h * HD + c4);
        v.x = f2tf(v.x); v.y = f2tf(v.y); v.z = f2tf(v.z); v.w = f2tf(v.w);
    }
    *(float4*)(g_vc + ((size_t)h * KCP + j) * HD + c4) = v;
}

// ---------------------------------------------------------------------------
// Flash attention over compact keys. Block = (q-tile of 128, head).
// 8 warps, each owns a 16-row q slab. TF32 mma for S=Q@K^T and O+=P@V.
// ---------------------------------------------------------------------------
#define ATT_STRIDE 136
#define ATT_SMEM_FLOATS (3 * 128 * ATT_STRIDE)

__global__ __launch_bounds__(256)
void attn_kernel()
{
    extern __shared__ float smem[];
    float* q_s  = smem;
    float* kv_s = smem + 128 * ATT_STRIDE;
    float* p_s  = smem + 2 * 128 * ATT_STRIDE;

    const int h = blockIdx.y, m0 = blockIdx.x * 128;
    const int tid = threadIdx.x, w = tid >> 5, lane = tid & 31;
    const int g = lane >> 2, tg = lane & 3;
    const int rb = w * 16;

    // Load Q tile (already rope'd/scaled/tf32)
    for (int i = tid; i < 128 * 32; i += 256) {
        int r = i >> 5, c = (i & 31) << 2;
        *(float4*)(q_s + r * ATT_STRIDE + c) =
            *(const float4*)(g_q + (size_t)(m0 + r) * HID + h * HD + c);
    }

    float mrow[2] = {-INFINITY, -INFINITY};
    float lrow[2] = {0.f, 0.f};
    float oacc[16][4];
    #pragma unroll
    for (int nt = 0; nt < 16; nt++)
        #pragma unroll
        for (int c = 0; c < 4; c++) oacc[nt][c] = 0.f;

    const float* kcb = g_kc + (size_t)h * KCP * HD;
    const float* vcb = g_vc + (size_t)h * KCP * HD;

    for (int kt = 0; kt < NKT; kt++) {
        __syncthreads();            // kv_s free (also covers q_s stores, kt=0)
        for (int i = tid; i < 128 * 32; i += 256) {
            int r = i >> 5, c = (i & 31) << 2;
            *(float4*)(kv_s + r * ATT_STRIDE + c) =
                *(const float4*)(kcb + (size_t)(kt * 128 + r) * HD + c);
        }
        __syncthreads();

        // S = Q @ K^T  (16 rows x 128 keys per warp)
        float sacc[16][4];
        #pragma unroll
        for (int nt = 0; nt < 16; nt++)
            #pragma unroll
            for (int c = 0; c < 4; c++) sacc[nt][c] = 0.f;

        #pragma unroll 2
        for (int ks = 0; ks < 16; ks++) {
            const int kk = ks << 3;
            uint32_t a0 = __float_as_uint(q_s[(rb + g    ) * ATT_STRIDE + kk + tg    ]);
            uint32_t a1 = __float_as_uint(q_s[(rb + g + 8) * ATT_STRIDE + kk + tg    ]);
            uint32_t a2 = __float_as_uint(q_s[(rb + g    ) * ATT_STRIDE + kk + tg + 4]);
            uint32_t a3 = __float_as_uint(q_s[(rb + g + 8) * ATT_STRIDE + kk + tg + 4]);
            #pragma unroll
            for (int nt = 0; nt < 16; nt++) {
                uint32_t b0 = __float_as_uint(kv_s[(nt * 8 + g) * ATT_STRIDE + kk + tg    ]);
                uint32_t b1 = __float_as_uint(kv_s[(nt * 8 + g) * ATT_STRIDE + kk + tg + 4]);
                mma_tf32(sacc[nt], a0, a1, a2, a3, b0, b1);
            }
        }

        // mask tail tile
        if (kt == NKT - 1) {
            #pragma unroll
            for (int nt = 0; nt < 16; nt++) {
                int j = kt * 128 + nt * 8 + tg * 2;
                #pragma unroll
                for (int c = 0; c < 4; c++)
                    if (j + (c & 1) >= KC) sacc[nt][c] = -INFINITY;
            }
        }

        // online softmax per row-half
        #pragma unroll
        for (int half = 0; half < 2; half++) {
            float mx = -INFINITY;
            #pragma unroll
            for (int nt = 0; nt < 16; nt++) {
                mx = fmaxf(mx, sacc[nt][2 * half]);
                mx = fmaxf(mx, sacc[nt][2 * half + 1]);
            }
            mx = fmaxf(mx, __shfl_xor_sync(0xffffffffu, mx, 1));
            mx = fmaxf(mx, __shfl_xor_sync(0xffffffffu, mx, 2));
            float mnew  = fmaxf(mrow[half], mx);
            float alpha = __expf(mrow[half] - mnew);
            mrow[half] = mnew;

            float rsum = 0.f;
            #pragma unroll
            for (int nt = 0; nt < 16; nt++) {
                float p0 = __expf(sacc[nt][2 * half]     - mnew);
                float p1 = __expf(sacc[nt][2 * half + 1] - mnew);
                rsum += p0 + p1;
                p_s[(rb + g + 8 * half) * ATT_STRIDE + nt * 8 + tg * 2]     = f2tf(p0);
                p_s[(rb + g + 8 * half) * ATT_STRIDE + nt * 8 + tg * 2 + 1] = f2tf(p1);
                oacc[nt][2 * half]     *= alpha;
                oacc[nt][2 * half + 1] *= alpha;
            }
            rsum += __shfl_xor_sync(0xffffffffu, rsum, 1);
            rsum += __shfl_xor_sync(0xffffffffu, rsum, 2);
            lrow[half] = lrow[half] * alpha + rsum;
        }

        __syncthreads();            // done reading K tile
        for (int i = tid; i < 128 * 32; i += 256) {
            int r = i >> 5, c = (i & 31) << 2;
            *(float4*)(kv_s + r * ATT_STRIDE + c) =
                *(const float4*)(vcb + (size_t)(kt * 128 + r) * HD + c);
        }
        __syncthreads();

        // O += P @ V
        #pragma unroll 2
        for (int ks = 0; ks < 16; ks++) {
            const int kk = ks << 3;
            uint32_t a0 = __float_as_uint(p_s[(rb + g    ) * ATT_STRIDE + kk + tg    ]);
            uint32_t a1 = __float_as_uint(p_s[(rb + g + 8) * ATT_STRIDE + kk + tg    ]);
            uint32_t a2 = __float_as_uint(p_s[(rb + g    ) * ATT_STRIDE + kk + tg + 4]);
            uint32_t a3 = __float_as_uint(p_s[(rb + g + 8) * ATT_STRIDE + kk + tg + 4]);
            #pragma unroll
            for (int nt = 0; nt < 16; nt++) {
                uint32_t b0 = __float_as_uint(kv_s[(kk + tg    ) * ATT_STRIDE + nt * 8 + g]);
                uint32_t b1 = __float_as_uint(kv_s[(kk + tg + 4) * ATT_STRIDE + nt * 8 + g]);
                mma_tf32(oacc[nt], a0, a1, a2, a3, b0, b1);
            }
        }
    }

    // write attention output [s][h*128+d]
    #pragma unroll
    for (int half = 0; half < 2; half++) {
        int r = m0 + rb + g + 8 * half;
        float inv_l = 1.f / lrow[half];
        #pragma unroll
        for (int nt = 0; nt < 16; nt++) {
            int c = h * HD + nt * 8 + tg * 2;
            float2 st = make_float2(oacc[nt][2 * half] * inv_l,
                                    oacc[nt][2 * half + 1] * inv_l);
            *(float2*)(g_ao + (size_t)r * HID + c) = st;
        }
    }
}

// ---------------------------------------------------------------------------
extern "C" void kernel_launch(void* const* d_in, const int* in_sizes, int n_in,
                              void* d_out, int out_size)
{
    const float* X  = (const float*)d_in[0];
    const float* Wq = (const float*)d_in[1];
    const float* bq = (const float*)d_in[2];
    const float* Wk = (const float*)d_in[3];
    const float* bk = (const float*)d_in[4];
    const float* Wv = (const float*)d_in[5];
    const float* bv = (const float*)d_in[6];
    const float* Wo = (const float*)d_in[7];
    const float* bo = (const float*)d_in[8];
    float* out = (float*)d_out;

    float *pq, *pk, *pv, *pao;
    cudaGetSymbolAddress((void**)&pq,  g_q);
    cudaGetSymbolAddress((void**)&pk,  g_k);
    cudaGetSymbolAddress((void**)&pv,  g_v);
    cudaGetSymbolAddress((void**)&pao, g_ao);

    dim3 ggrid(HID / 128, SEQ / 128);
    gemm_tn<<<ggrid, 256>>>(X, Wq, bq, pq, SEQ, HID, HID);
    gemm_tn<<<ggrid, 256>>>(X, Wk, bk, pk, SEQ, HID, HID);
    gemm_tn<<<ggrid, 256>>>(X, Wv, bv, pv, SEQ, HID, HID);

    theta_kernel<<<1, 64>>>();
    rope_q_kernel<<<SEQ * HEADS * 32 / 256, 256>>>();
    rope_kc_kernel<<<HEADS * KCP * 32 / 256, 256>>>();
    copy_vc_kernel<<<HEADS * KCP * 32 / 256, 256>>>();

    int smem_bytes = ATT_SMEM_FLOATS * (int)sizeof(float);
    cudaFuncSetAttribute(attn_kernel, cudaFuncAttributeMaxDynamicSharedMemorySize, smem_bytes);
    attn_kernel<<<dim3(SEQ / 128, HEADS), 256, smem_bytes>>>();

    gemm_tn<<<ggrid, 256>>>(pao, Wo, bo, out, SEQ, HID, HID);
}

// round 2
// speedup vs baseline: 1.1213x; 1.1213x over previous
#include <cuda_runtime.h>
#include <cuda_bf16.h>
#include <math.h>
#include <stdint.h>

// ---------------------------------------------------------------------------
// MiniGPT4AttentionCam: B=1, S=4096, HID=2048, 16 heads x 128
// CAM mask: keys [0,410) U [3072,4096)  (non-causal, query-independent)
// R2: 3-stage cp.async pipelined TF32 GEMM, preconverted tf32 operands,
//     RoPE fused into Q/K GEMM epilogues.
// ---------------------------------------------------------------------------

#define SEQ    4096
#define HID    2048
#define HEADS  16
#define HD     128
#define SB     410
#define RSTART 3072
#define KC     1434
#define KCP    1536
#define NKT    12

// Scratch (device globals)
__device__ float g_q  [(size_t)SEQ * HID];
__device__ float g_k  [(size_t)SEQ * HID];
__device__ float g_v  [(size_t)SEQ * HID];
__device__ float g_kc [(size_t)HEADS * KCP * HD];
__device__ float g_vc [(size_t)HEADS * KCP * HD];
__device__ float g_ao [(size_t)SEQ * HID];
__device__ float g_xt [(size_t)SEQ * HID];          // X in tf32
__device__ float g_wt [(size_t)4 * HID * HID];      // Wq,Wk,Wv,Wo in tf32
__device__ float g_theta[64];

__device__ __forceinline__ float f2tf(float x) {
    uint32_t r;
    asm("cvt.rna.tf32.f32 %0, %1;" : "=r"(r) : "f"(x));
    return __uint_as_float(r);
}

__device__ __forceinline__ uint32_t s2u(const void* p) {
    uint32_t a;
    asm("{ .reg .u64 t; cvta.to.shared.u64 t, %1; cvt.u32.u64 %0, t; }"
        : "=r"(a) : "l"(p));
    return a;
}

__device__ __forceinline__ void cp16(uint32_t s, const void* g) {
    asm volatile("cp.async.ca.shared.global [%0], [%1], 16;\n" :: "r"(s), "l"(g));
}
__device__ __forceinline__ void cp_commit() {
    asm volatile("cp.async.commit_group;\n");
}
template<int N>
__device__ __forceinline__ void cp_wait() {
    asm volatile("cp.async.wait_group %0;\n" :: "n"(N));
}

__device__ __forceinline__ void mma_tf32(float c[4],
    uint32_t a0, uint32_t a1, uint32_t a2, uint32_t a3,
    uint32_t b0, uint32_t b1)
{
    asm volatile(
        "mma.sync.aligned.m16n8k8.row.col.f32.tf32.tf32.f32 "
        "{%0,%1,%2,%3}, {%4,%5,%6,%7}, {%8,%9}, {%0,%1,%2,%3};\n"
        : "+f"(c[0]), "+f"(c[1]), "+f"(c[2]), "+f"(c[3])
        : "r"(a0), "r"(a1), "r"(a2), "r"(a3), "r"(b0), "r"(b1));
}

// ---------------------------------------------------------------------------
// Preconvert kernels (rna tf32 rounding done once, outside GEMM hot loop)
// ---------------------------------------------------------------------------
__global__ void conv_w(const float* __restrict__ Wq, const float* __restrict__ Wk,
                       const float* __restrict__ Wv, const float* __restrict__ Wo)
{
    int a = blockIdx.y;
    const float* src = (a == 0) ? Wq : (a == 1) ? Wk : (a == 2) ? Wv : Wo;
    float* dst = g_wt + (size_t)a * HID * HID;
    size_t i = ((size_t)blockIdx.x * blockDim.x + threadIdx.x) * 4;
    float4 v = *(const float4*)(src + i);
    v.x = f2tf(v.x); v.y = f2tf(v.y); v.z = f2tf(v.z); v.w = f2tf(v.w);
    *(float4*)(dst + i) = v;
}

__global__ void conv_x(const float* __restrict__ X)
{
    size_t i = ((size_t)blockIdx.x * blockDim.x + threadIdx.x) * 4;
    float4 v = *(const float4*)(X + i);
    v.x = f2tf(v.x); v.y = f2tf(v.y); v.z = f2tf(v.z); v.w = f2tf(v.w);
    *(float4*)(g_xt + i) = v;
}

__global__ void theta_kernel() {
    int p = threadIdx.x;
    if (p < 64) g_theta[p] = (float)pow(10000.0, -(double)p / 64.0);
}

// ---------------------------------------------------------------------------
// Pipelined GEMM: C[4096,2048] = A[4096,2048] @ B[2048,2048]^T + bias
// 128x128 tile, BK=32, 3-stage cp.async, 256 thr, warp 32x64 (4m x 2n).
// MODE 0: plain fp32 out. MODE 1: RoPE+scale+tf32 (Q). MODE 2: RoPE+tf32 (K).
// MODE 3: +bias, tf32 (V).
// ---------------------------------------------------------------------------
#define GST    36                    // smem row stride (floats)
#define GATILE (128 * GST)
#define GSTAGE (2 * GATILE)
#define GSMEM_BYTES (3 * GSTAGE * 4)

template<int MODE>
__global__ void __launch_bounds__(256, 2)
gemm_tn(const float* __restrict__ A, const float* __restrict__ B,
        const float* __restrict__ bias, float* __restrict__ C)
{
    extern __shared__ float sm[];
    const int tid = threadIdx.x, w = tid >> 5, lane = tid & 31;
    const int g = lane >> 2, tg = lane & 3;
    const int wm = w & 3, wn = w >> 2;
    const int m0 = blockIdx.y * 128, n0 = blockIdx.x * 128;

    const uint32_t sb = s2u(sm);
    const int rbase = tid >> 3;            // row within tile for loads
    const int cc    = (tid & 7) << 2;      // col (float4) within BK
    const float* gA = A + (size_t)(m0 + rbase) * HID + cc;
    const float* gB = B + (size_t)(n0 + rbase) * HID + cc;
    const uint32_t sA0 = sb + (uint32_t)(rbase * GST + cc) * 4;

    float acc[2][8][4];
    #pragma unroll
    for (int a = 0; a < 2; a++)
        #pragma unroll
        for (int b = 0; b < 8; b++)
            #pragma unroll
            for (int q = 0; q < 4; q++) acc[a][b][q] = 0.f;

    auto LOAD = [&](int st, int kt) {
        const float* a = gA + kt * 32;
        const float* b = gB + kt * 32;
        uint32_t s = sA0 + (uint32_t)(st * GSTAGE) * 4;
        #pragma unroll
        for (int i = 0; i < 4; i++) {
            cp16(s + (uint32_t)(i * 32 * GST) * 4,              a + (size_t)i * 32 * HID);
            cp16(s + (uint32_t)(GATILE + i * 32 * GST) * 4,     b + (size_t)i * 32 * HID);
        }
        cp_commit();
    };

    LOAD(0, 0);
    LOAD(1, 1);
    cp_wait<1>();
    __syncthreads();

    int st = 0, ld = 2;
    for (int kt = 0; kt < 64; kt++) {
        const float* sA = sm + st * GSTAGE;
        const float* sB = sA + GATILE;

        #pragma unroll
        for (int ks = 0; ks < 4; ks++) {
            const int kk = ks << 3;
            uint32_t af[2][4], bf[8][2];
            #pragma unroll
            for (int mt = 0; mt < 2; mt++) {
                int rb = wm * 32 + mt * 16;
                af[mt][0] = __float_as_uint(sA[(rb + g    ) * GST + kk + tg    ]);
                af[mt][1] = __float_as_uint(sA[(rb + g + 8) * GST + kk + tg    ]);
                af[mt][2] = __float_as_uint(sA[(rb + g    ) * GST + kk + tg + 4]);
                af[mt][3] = __float_as_uint(sA[(rb + g + 8) * GST + kk + tg + 4]);
            }
            #pragma unroll
            for (int nt = 0; nt < 8; nt++) {
                int nb = wn * 64 + nt * 8;
                bf[nt][0] = __float_as_uint(sB[(nb + g) * GST + kk + tg    ]);
                bf[nt][1] = __float_as_uint(sB[(nb + g) * GST + kk + tg + 4]);
            }
            #pragma unroll
            for (int mt = 0; mt < 2; mt++)
                #pragma unroll
                for (int nt = 0; nt < 8; nt++)
                    mma_tf32(acc[mt][nt], af[mt][0], af[mt][1], af[mt][2], af[mt][3],
                             bf[nt][0], bf[nt][1]);
        }

        if (kt + 2 < 64) {
            LOAD(ld, kt + 2);
            ld = (ld == 2) ? 0 : ld + 1;
        } else {
            cp_commit();
        }
        cp_wait<1>();
        __syncthreads();
        st = (st == 2) ? 0 : st + 1;
    }

    // ---- epilogue ----
    if (MODE == 0 || MODE == 3) {
        #pragma unroll
        for (int mt = 0; mt < 2; mt++) {
            int r0 = m0 + wm * 32 + mt * 16 + g;
            #pragma unroll
            for (int nt = 0; nt < 8; nt++) {
                int c = n0 + wn * 64 + nt * 8 + tg * 2;
                float2 b2 = *(const float2*)(bias + c);
                float o0 = acc[mt][nt][0] + b2.x, o1 = acc[mt][nt][1] + b2.y;
                float o2 = acc[mt][nt][2] + b2.x, o3 = acc[mt][nt][3] + b2.y;
                if (MODE == 3) { o0 = f2tf(o0); o1 = f2tf(o1); o2 = f2tf(o2); o3 = f2tf(o3); }
                *(float2*)(C + (size_t)r0 * HID + c)       = make_float2(o0, o1);
                *(float2*)(C + (size_t)(r0 + 8) * HID + c) = make_float2(o2, o3);
            }
        }
    } else {
        const float SC = (MODE == 1) ? 0.08838834764831845f : 1.0f;
        #pragma unroll
        for (int mt = 0; mt < 2; mt++) {
            int r0 = m0 + wm * 32 + mt * 16 + g;
            #pragma unroll
            for (int nt = 0; nt < 8; nt++) {
                int c = n0 + wn * 64 + nt * 8 + tg * 2;
                int hb = c & ~127;
                int p  = (c & 127) >> 1;
                float th = g_theta[p];
                float y1a = acc[mt][nt][0] + bias[c];
                float y2a = acc[mt][nt][1] + bias[c + 1];
                float y1b = acc[mt][nt][2] + bias[c];
                float y2b = acc[mt][nt][3] + bias[c + 1];
                float sn, cs;
                sincosf((float)r0 * th, &sn, &cs);
                C[(size_t)r0 * HID + hb + p]      = f2tf((y1a * cs - y2a * sn) * SC);
                C[(size_t)r0 * HID + hb + p + 64] = f2tf((y1a * sn + y2a * cs) * SC);
                sincosf((float)(r0 + 8) * th, &sn, &cs);
                C[(size_t)(r0 + 8) * HID + hb + p]      = f2tf((y1b * cs - y2b * sn) * SC);
                C[(size_t)(r0 + 8) * HID + hb + p + 64] = f2tf((y1b * sn + y2b * cs) * SC);
            }
        }
    }
}

// ---------------------------------------------------------------------------
// Gather compact K/V (K already RoPE'd+tf32 by epilogue; V already tf32)
// ---------------------------------------------------------------------------
__global__ void gather_kv() {
    int idx = blockIdx.x * blockDim.x + threadIdx.x;   // float4 granularity
    if (idx >= HEADS * KCP * 32) return;
    int c4  = (idx & 31) * 4;
    int row = idx >> 5;
    int h = row / KCP, j = row % KCP;
    float4 vk = make_float4(0.f, 0.f, 0.f, 0.f);
    float4 vv = vk;
    if (j < KC) {
        int s = (j < SB) ? j : (RSTART + (j - SB));
        size_t off = (size_t)s * HID + h * HD + c4;
        vk = *(const float4*)(g_k + off);
        vv = *(const float4*)(g_v + off);
    }
    size_t doff = (size_t)row * HD + c4;
    *(float4*)(g_kc + doff) = vk;
    *(float4*)(g_vc + doff) = vv;
}

// ---------------------------------------------------------------------------
// Flash attention over compact keys (unchanged structure from R1; AO now tf32)
// ---------------------------------------------------------------------------
#define ATT_STRIDE 136
#define ATT_SMEM_FLOATS (3 * 128 * ATT_STRIDE)

__global__ __launch_bounds__(256)
void attn_kernel()
{
    extern __shared__ float smem[];
    float* q_s  = smem;
    float* kv_s = smem + 128 * ATT_STRIDE;
    float* p_s  = smem + 2 * 128 * ATT_STRIDE;

    const int h = blockIdx.y, m0 = blockIdx.x * 128;
    const int tid = threadIdx.x, w = tid >> 5, lane = tid & 31;
    const int g = lane >> 2, tg = lane & 3;
    const int rb = w * 16;

    for (int i = tid; i < 128 * 32; i += 256) {
        int r = i >> 5, c = (i & 31) << 2;
        *(float4*)(q_s + r * ATT_STRIDE + c) =
            *(const float4*)(g_q + (size_t)(m0 + r) * HID + h * HD + c);
    }

    float mrow[2] = {-INFINITY, -INFINITY};
    float lrow[2] = {0.f, 0.f};
    float oacc[16][4];
    #pragma unroll
    for (int nt = 0; nt < 16; nt++)
        #pragma unroll
        for (int c = 0; c < 4; c++) oacc[nt][c] = 0.f;

    const float* kcb = g_kc + (size_t)h * KCP * HD;
    const float* vcb = g_vc + (size_t)h * KCP * HD;

    for (int kt = 0; kt < NKT; kt++) {
        __syncthreads();
        for (int i = tid; i < 128 * 32; i += 256) {
            int r = i >> 5, c = (i & 31) << 2;
            *(float4*)(kv_s + r * ATT_STRIDE + c) =
                *(const float4*)(kcb + (size_t)(kt * 128 + r) * HD + c);
        }
        __syncthreads();

        float sacc[16][4];
        #pragma unroll
        for (int nt = 0; nt < 16; nt++)
            #pragma unroll
            for (int c = 0; c < 4; c++) sacc[nt][c] = 0.f;

        #pragma unroll 2
        for (int ks = 0; ks < 16; ks++) {
            const int kk = ks << 3;
            uint32_t a0 = __float_as_uint(q_s[(rb + g    ) * ATT_STRIDE + kk + tg    ]);
            uint32_t a1 = __float_as_uint(q_s[(rb + g + 8) * ATT_STRIDE + kk + tg    ]);
            uint32_t a2 = __float_as_uint(q_s[(rb + g    ) * ATT_STRIDE + kk + tg + 4]);
            uint32_t a3 = __float_as_uint(q_s[(rb + g + 8) * ATT_STRIDE + kk + tg + 4]);
            #pragma unroll
            for (int nt = 0; nt < 16; nt++) {
                uint32_t b0 = __float_as_uint(kv_s[(nt * 8 + g) * ATT_STRIDE + kk + tg    ]);
                uint32_t b1 = __float_as_uint(kv_s[(nt * 8 + g) * ATT_STRIDE + kk + tg + 4]);
                mma_tf32(sacc[nt], a0, a1, a2, a3, b0, b1);
            }
        }

        if (kt == NKT - 1) {
            #pragma unroll
            for (int nt = 0; nt < 16; nt++) {
                int j = kt * 128 + nt * 8 + tg * 2;
                #pragma unroll
                for (int c = 0; c < 4; c++)
                    if (j + (c & 1) >= KC) sacc[nt][c] = -INFINITY;
            }
        }

        #pragma unroll
        for (int half = 0; half < 2; half++) {
            float mx = -INFINITY;
            #pragma unroll
            for (int nt = 0; nt < 16; nt++) {
                mx = fmaxf(mx, sacc[nt][2 * half]);
                mx = fmaxf(mx, sacc[nt][2 * half + 1]);
            }
            mx = fmaxf(mx, __shfl_xor_sync(0xffffffffu, mx, 1));
            mx = fmaxf(mx, __shfl_xor_sync(0xffffffffu, mx, 2));
            float mnew  = fmaxf(mrow[half], mx);
            float alpha = __expf(mrow[half] - mnew);
            mrow[half] = mnew;

            float rsum = 0.f;
            #pragma unroll
            for (int nt = 0; nt < 16; nt++) {
                float p0 = __expf(sacc[nt][2 * half]     - mnew);
                float p1 = __expf(sacc[nt][2 * half + 1] - mnew);
                rsum += p0 + p1;
                p_s[(rb + g + 8 * half) * ATT_STRIDE + nt * 8 + tg * 2]     = f2tf(p0);
                p_s[(rb + g + 8 * half) * ATT_STRIDE + nt * 8 + tg * 2 + 1] = f2tf(p1);
                oacc[nt][2 * half]     *= alpha;
                oacc[nt][2 * half + 1] *= alpha;
            }
            rsum += __shfl_xor_sync(0xffffffffu, rsum, 1);
            rsum += __shfl_xor_sync(0xffffffffu, rsum, 2);
            lrow[half] = lrow[half] * alpha + rsum;
        }

        __syncthreads();
        for (int i = tid; i < 128 * 32; i += 256) {
            int r = i >> 5, c = (i & 31) << 2;
            *(float4*)(kv_s + r * ATT_STRIDE + c) =
                *(const float4*)(vcb + (size_t)(kt * 128 + r) * HD + c);
        }
        __syncthreads();

        #pragma unroll 2
        for (int ks = 0; ks < 16; ks++) {
            const int kk = ks << 3;
            uint32_t a0 = __float_as_uint(p_s[(rb + g    ) * ATT_STRIDE + kk + tg    ]);
            uint32_t a1 = __float_as_uint(p_s[(rb + g + 8) * ATT_STRIDE + kk + tg    ]);
            uint32_t a2 = __float_as_uint(p_s[(rb + g    ) * ATT_STRIDE + kk + tg + 4]);
            uint32_t a3 = __float_as_uint(p_s[(rb + g + 8) * ATT_STRIDE + kk + tg + 4]);
            #pragma unroll
            for (int nt = 0; nt < 16; nt++) {
                uint32_t b0 = __float_as_uint(kv_s[(kk + tg    ) * ATT_STRIDE + nt * 8 + g]);
                uint32_t b1 = __float_as_uint(kv_s[(kk + tg + 4) * ATT_STRIDE + nt * 8 + g]);
                mma_tf32(oacc[nt], a0, a1, a2, a3, b0, b1);
            }
        }
    }

    #pragma unroll
    for (int half = 0; half < 2; half++) {
        int r = m0 + rb + g + 8 * half;
        float inv_l = 1.f / lrow[half];
        #pragma unroll
        for (int nt = 0; nt < 16; nt++) {
            int c = h * HD + nt * 8 + tg * 2;
            float2 st = make_float2(f2tf(oacc[nt][2 * half] * inv_l),
                                    f2tf(oacc[nt][2 * half + 1] * inv_l));
            *(float2*)(g_ao + (size_t)r * HID + c) = st;
        }
    }
}

// ---------------------------------------------------------------------------
extern "C" void kernel_launch(void* const* d_in, const int* in_sizes, int n_in,
                              void* d_out, int out_size)
{
    const float* X  = (const float*)d_in[0];
    const float* Wq = (const float*)d_in[1];
    const float* bq = (const float*)d_in[2];
    const float* Wk = (const float*)d_in[3];
    const float* bk = (const float*)d_in[4];
    const float* Wv = (const float*)d_in[5];
    const float* bv = (const float*)d_in[6];
    const float* Wo = (const float*)d_in[7];
    const float* bo = (const float*)d_in[8];
    float* out = (float*)d_out;

    float *pq, *pk, *pv, *pao, *pxt, *pwt;
    cudaGetSymbolAddress((void**)&pq,  g_q);
    cudaGetSymbolAddress((void**)&pk,  g_k);
    cudaGetSymbolAddress((void**)&pv,  g_v);
    cudaGetSymbolAddress((void**)&pao, g_ao);
    cudaGetSymbolAddress((void**)&pxt, g_xt);
    cudaGetSymbolAddress((void**)&pwt, g_wt);

    cudaFuncSetAttribute(gemm_tn<0>, cudaFuncAttributeMaxDynamicSharedMemorySize, GSMEM_BYTES);
    cudaFuncSetAttribute(gemm_tn<1>, cudaFuncAttributeMaxDynamicSharedMemorySize, GSMEM_BYTES);
    cudaFuncSetAttribute(gemm_tn<2>, cudaFuncAttributeMaxDynamicSharedMemorySize, GSMEM_BYTES);
    cudaFuncSetAttribute(gemm_tn<3>, cudaFuncAttributeMaxDynamicSharedMemorySize, GSMEM_BYTES);

    // preconvert to tf32
    conv_w<<<dim3(HID * HID / (256 * 4), 4), 256>>>(Wq, Wk, Wv, Wo);
    conv_x<<<SEQ * HID / (256 * 4), 256>>>(X);
    theta_kernel<<<1, 64>>>();

    dim3 ggrid(HID / 128, SEQ / 128);
    gemm_tn<2><<<ggrid, 256, GSMEM_BYTES>>>(pxt, pwt + (size_t)1 * HID * HID, bk, pk);
    gemm_tn<3><<<ggrid, 256, GSMEM_BYTES>>>(pxt, pwt + (size_t)2 * HID * HID, bv, pv);
    gemm_tn<1><<<ggrid, 256, GSMEM_BYTES>>>(pxt, pwt + (size_t)0 * HID * HID, bq, pq);

    gather_kv<<<HEADS * KCP * 32 / 256, 256>>>();

    int smem_bytes = ATT_SMEM_FLOATS * (int)sizeof(float);
    cudaFuncSetAttribute(attn_kernel, cudaFuncAttributeMaxDynamicSharedMemorySize, smem_bytes);
    attn_kernel<<<dim3(SEQ / 128, HEADS), 256, smem_bytes>>>();

    gemm_tn<0><<<ggrid, 256, GSMEM_BYTES>>>(pao, pwt + (size_t)3 * HID * HID, bo, out);
}

// round 8
// speedup vs baseline: 2.7131x; 2.4197x over previous
#include <cuda_runtime.h>
#include <cuda_fp16.h>
#include <math.h>
#include <stdint.h>

// ---------------------------------------------------------------------------
// MiniGPT4AttentionCam  (B=1, S=4096, HID=2048, 16 heads x 128)
// R8 (= R7 resubmit; R7 hit an infra-level container failure, kernel unjudged)
//     sm_100 BASE target: fp16 mma.sync.m16n8k16 + ldmatrix + cp.async.
//     GEMMs: 128x128 tile, BK=64, 3-stage. RoPE fused in Q/K epilogues.
//     Attention: flash over compact 1536 keys, ldmatrix (trans for V).
// ---------------------------------------------------------------------------

#define SEQ    4096
#define HID    2048
#define HEADS  16
#define HD     128
#define SB     410
#define RSTART 3072
#define KC     1434
#define KCP    1536
#define NKT    12

// Scratch (fp16 everywhere)
__device__ __half g_q [(size_t)SEQ * HID];
__device__ __half g_k [(size_t)SEQ * HID];
__device__ __half g_v [(size_t)SEQ * HID];
__device__ __half g_ao[(size_t)SEQ * HID];
__device__ __half g_kc[(size_t)HEADS * KCP * HD];
__device__ __half g_vc[(size_t)HEADS * KCP * HD];
__device__ __half g_xh[(size_t)SEQ * HID];
__device__ __half g_wh[(size_t)4 * HID * HID];
__device__ float  g_theta[64];

// ---------------- helpers ----------------
__device__ __forceinline__ uint32_t s2u(const void* p) {
    uint32_t a;
    asm("{ .reg .u64 t; cvta.to.shared.u64 t, %1; cvt.u32.u64 %0, t; }"
        : "=r"(a) : "l"(p));
    return a;
}
__device__ __forceinline__ void cp16(uint32_t s, const void* g) {
    asm volatile("cp.async.ca.shared.global [%0], [%1], 16;\n" :: "r"(s), "l"(g));
}
__device__ __forceinline__ void cp_commit() {
    asm volatile("cp.async.commit_group;\n");
}
template<int N>
__device__ __forceinline__ void cp_wait() {
    asm volatile("cp.async.wait_group %0;\n" :: "n"(N));
}

#define SWZ128(o) ((o) ^ (((o) >> 3) & 0x70))

__device__ __forceinline__ void ldsm4(uint32_t& r0, uint32_t& r1, uint32_t& r2,
                                      uint32_t& r3, uint32_t addr) {
    asm volatile("ldmatrix.sync.aligned.m8n8.x4.shared.b16 {%0,%1,%2,%3}, [%4];"
        : "=r"(r0), "=r"(r1), "=r"(r2), "=r"(r3) : "r"(addr));
}
__device__ __forceinline__ void ldsm4t(uint32_t& r0, uint32_t& r1, uint32_t& r2,
                                       uint32_t& r3, uint32_t addr) {
    asm volatile("ldmatrix.sync.aligned.m8n8.x4.trans.shared.b16 {%0,%1,%2,%3}, [%4];"
        : "=r"(r0), "=r"(r1), "=r"(r2), "=r"(r3) : "r"(addr));
}
__device__ __forceinline__ void mma_f16(float c[4],
    uint32_t a0, uint32_t a1, uint32_t a2, uint32_t a3,
    uint32_t b0, uint32_t b1)
{
    asm volatile(
        "mma.sync.aligned.m16n8k16.row.col.f32.f16.f16.f32 "
        "{%0,%1,%2,%3}, {%4,%5,%6,%7}, {%8,%9}, {%0,%1,%2,%3};\n"
        : "+f"(c[0]), "+f"(c[1]), "+f"(c[2]), "+f"(c[3])
        : "r"(a0), "r"(a1), "r"(a2), "r"(a3), "r"(b0), "r"(b1));
}

// ---------------------------------------------------------------------------
// Pre-convert to fp16
// ---------------------------------------------------------------------------
__global__ void conv_w(const float* __restrict__ Wq, const float* __restrict__ Wk,
                       const float* __restrict__ Wv, const float* __restrict__ Wo)
{
    int a = blockIdx.y;
    const float* src = (a == 0) ? Wq : (a == 1) ? Wk : (a == 2) ? Wv : Wo;
    size_t i = ((size_t)blockIdx.x * blockDim.x + threadIdx.x) * 4;
    float4 v = *(const float4*)(src + i);
    __half* d = g_wh + (size_t)a * HID * HID + i;
    *(__half2*)(d)     = __floats2half2_rn(v.x, v.y);
    *(__half2*)(d + 2) = __floats2half2_rn(v.z, v.w);
}

__global__ void conv_x(const float* __restrict__ X)
{
    size_t i = ((size_t)blockIdx.x * blockDim.x + threadIdx.x) * 4;
    float4 v = *(const float4*)(X + i);
    *(__half2*)(g_xh + i)     = __floats2half2_rn(v.x, v.y);
    *(__half2*)(g_xh + i + 2) = __floats2half2_rn(v.z, v.w);
}

__global__ void theta_kernel() {
    int p = threadIdx.x;
    if (p < 64) g_theta[p] = (float)pow(10000.0, -(double)p / 64.0);
}

// ---------------------------------------------------------------------------
// fp16 GEMM: C[4096,2048] = A[4096,2048] @ B[2048,2048]^T + bias
// 128x128 tile, BK=64 (128B rows, SW128), 3-stage cp.async, 256 thr,
// 8 warps (4m x 2n), warp tile 32x64, mma m16n8k16 via ldmatrix.
// MODE: 0=O(float out) 1=Q(rope+scale,fp16) 2=K(rope,fp16) 3=V(fp16)
// ---------------------------------------------------------------------------
#define GTILE_B  16384
#define GSTAGE_B 32768
#define GSMEM    (3 * GSTAGE_B)     // 98304 B
#define NTILES   32                 // 2048 / 64

template<int MODE>
__global__ void __launch_bounds__(256, 2)
gemm_f16(const __half* __restrict__ A, const __half* __restrict__ B,
         const float* __restrict__ bias, void* __restrict__ Cout)
{
    extern __shared__ char smem[];
    const uint32_t su = s2u(smem);
    const int tid = threadIdx.x, w = tid >> 5, lane = tid & 31;
    const int g = lane >> 2, tg = lane & 3;
    const int wm = w & 3, wn = w >> 2;
    const int m0 = blockIdx.y * 128, n0 = blockIdx.x * 128;

    float acc[2][8][4];
    #pragma unroll
    for (int a = 0; a < 2; a++)
        #pragma unroll
        for (int b = 0; b < 8; b++)
            #pragma unroll
            for (int q = 0; q < 4; q++) acc[a][b][q] = 0.f;

    const int la7 = lane & 7;
    const int arow  = wm * 32 + la7 + (lane & 8);        // + mt*16
    const int acol2 = lane & 16;                         // byte add
    const int brow0 = wn * 64 + la7 + ((lane & 16) >> 1);// + np*16
    const int bcol2 = (lane & 8) * 2;

    const char* gA = (const char*)A;
    const char* gB = (const char*)B;

    auto FILL = [&](int st, int kt) {
        uint32_t sb = su + st * GSTAGE_B;
        #pragma unroll
        for (int i = 0; i < 4; i++) {
            int idx = tid + i * 256;
            int m = idx >> 3, c = (idx & 7) << 4;
            uint32_t so = SWZ128((uint32_t)(m * 128 + c));
            cp16(sb + so,           gA + (size_t)(m0 + m) * (HID * 2) + kt * 128 + c);
            cp16(sb + GTILE_B + so, gB + (size_t)(n0 + m) * (HID * 2) + kt * 128 + c);
        }
        cp_commit();
    };

    FILL(0, 0);
    FILL(1, 1);
    cp_wait<1>();
    __syncthreads();

    int st = 0, ld = 2;
    for (int kt = 0; kt < NTILES; kt++) {
        uint32_t sA = su + st * GSTAGE_B;
        uint32_t sB = sA + GTILE_B;

        #pragma unroll
        for (int ks = 0; ks < 4; ks++) {
            const int kk2 = ks * 32;
            uint32_t a[2][4];
            #pragma unroll
            for (int mt = 0; mt < 2; mt++) {
                uint32_t off = SWZ128((uint32_t)((arow + mt * 16) * 128 + kk2 + acol2));
                ldsm4(a[mt][0], a[mt][1], a[mt][2], a[mt][3], sA + off);
            }
            uint32_t b[8][2];
            #pragma unroll
            for (int np = 0; np < 4; np++) {
                uint32_t off = SWZ128((uint32_t)((brow0 + np * 16) * 128 + kk2 + bcol2));
                uint32_t r0, r1, r2, r3;
                ldsm4(r0, r1, r2, r3, sB + off);
                b[2 * np][0] = r0; b[2 * np][1] = r1;
                b[2 * np + 1][0] = r2; b[2 * np + 1][1] = r3;
            }
            #pragma unroll
            for (int mt = 0; mt < 2; mt++)
                #pragma unroll
                for (int nt = 0; nt < 8; nt++)
                    mma_f16(acc[mt][nt], a[mt][0], a[mt][1], a[mt][2], a[mt][3],
                            b[nt][0], b[nt][1]);
        }

        if (kt + 2 < NTILES) {
            FILL(ld, kt + 2);
            ld = (ld == 2) ? 0 : ld + 1;
        } else {
            cp_commit();
        }
        cp_wait<1>();
        __syncthreads();
        st = (st == 2) ? 0 : st + 1;
    }

    // ---- epilogue ----
    if (MODE == 0) {
        float* C = (float*)Cout;
        #pragma unroll
        for (int mt = 0; mt < 2; mt++) {
            int r0 = m0 + wm * 32 + mt * 16 + g;
            #pragma unroll
            for (int nt = 0; nt < 8; nt++) {
                int c = n0 + wn * 64 + nt * 8 + tg * 2;
                float2 b2 = *(const float2*)(bias + c);
                *(float2*)(C + (size_t)r0 * HID + c) =
                    make_float2(acc[mt][nt][0] + b2.x, acc[mt][nt][1] + b2.y);
                *(float2*)(C + (size_t)(r0 + 8) * HID + c) =
                    make_float2(acc[mt][nt][2] + b2.x, acc[mt][nt][3] + b2.y);
            }
        }
    } else if (MODE == 3) {
        __half* C = (__half*)Cout;
        #pragma unroll
        for (int mt = 0; mt < 2; mt++) {
            int r0 = m0 + wm * 32 + mt * 16 + g;
            #pragma unroll
            for (int nt = 0; nt < 8; nt++) {
                int c = n0 + wn * 64 + nt * 8 + tg * 2;
                float2 b2 = *(const float2*)(bias + c);
                *(__half2*)(C + (size_t)r0 * HID + c) =
                    __floats2half2_rn(acc[mt][nt][0] + b2.x, acc[mt][nt][1] + b2.y);
                *(__half2*)(C + (size_t)(r0 + 8) * HID + c) =
                    __floats2half2_rn(acc[mt][nt][2] + b2.x, acc[mt][nt][3] + b2.y);
            }
        }
    } else {
        __half* C = (__half*)Cout;
        const float SC = (MODE == 1) ? 0.08838834764831845f : 1.0f;
        #pragma unroll
        for (int mt = 0; mt < 2; mt++) {
            int r0 = m0 + wm * 32 + mt * 16 + g;
            #pragma unroll
            for (int nt = 0; nt < 8; nt++) {
                int c = n0 + wn * 64 + nt * 8 + tg * 2;
                int hb = c & ~127;
                int p  = (c & 127) >> 1;
                float th = g_theta[p];
                float y1a = acc[mt][nt][0] + bias[c];
                float y2a = acc[mt][nt][1] + bias[c + 1];
                float y1b = acc[mt][nt][2] + bias[c];
                float y2b = acc[mt][nt][3] + bias[c + 1];
                float sn, cs;
                sincosf((float)r0 * th, &sn, &cs);
                C[(size_t)r0 * HID + hb + p]      = __float2half_rn((y1a * cs - y2a * sn) * SC);
                C[(size_t)r0 * HID + hb + p + 64] = __float2half_rn((y1a * sn + y2a * cs) * SC);
                sincosf((float)(r0 + 8) * th, &sn, &cs);
                C[(size_t)(r0 + 8) * HID + hb + p]      = __float2half_rn((y1b * cs - y2b * sn) * SC);
                C[(size_t)(r0 + 8) * HID + hb + p + 64] = __float2half_rn((y1b * sn + y2b * cs) * SC);
            }
        }
    }
}

// ---------------------------------------------------------------------------
// Gather compact K/V (fp16, 16B chunks)
// ---------------------------------------------------------------------------
__global__ void gather_kv() {
    int idx = blockIdx.x * blockDim.x + threadIdx.x;   // 16B granularity
    if (idx >= HEADS * KCP * 16) return;
    int c8  = (idx & 15) * 8;          // halves offset within row
    int row = idx >> 4;
    int h = row / KCP, j = row % KCP;
    uint4 vk = make_uint4(0, 0, 0, 0);
    uint4 vv = vk;
    if (j < KC) {
        int s = (j < SB) ? j : (RSTART + (j - SB));
        size_t off = (size_t)s * HID + h * HD + c8;
        vk = *(const uint4*)(g_k + off);
        vv = *(const uint4*)(g_v + off);
    }
    size_t doff = (size_t)row * HD + c8;
    *(uint4*)(g_kc + doff) = vk;
    *(uint4*)(g_vc + doff) = vv;
}

// ---------------------------------------------------------------------------
// Flash attention over compact keys (fp16 mma + ldmatrix; trans-ldmatrix V)
// Block = (q-tile 128, head). 8 warps x 16 q-rows.
// ---------------------------------------------------------------------------
#define QST 136                          // halves per smem row (272 B)
#define ATT_SMEM_B (3 * 128 * QST * 2)   // 104448 B

__global__ __launch_bounds__(256, 1)
void attn_kernel()
{
    extern __shared__ __half smem_att[];
    __half* q_s  = smem_att;
    __half* kv_s = smem_att + 128 * QST;
    __half* p_s  = smem_att + 2 * 128 * QST;
    const uint32_t qu  = s2u(q_s);
    const uint32_t kvu = s2u(kv_s);
    const uint32_t pu  = s2u(p_s);

    const int h = blockIdx.y, m0 = blockIdx.x * 128;
    const int tid = threadIdx.x, w = tid >> 5, lane = tid & 31;
    const int g = lane >> 2, tg = lane & 3;
    const int rb = w * 16;
    const int la7 = lane & 7;

    // ldmatrix lane-role offsets
    const int aro  = rb + la7 + (lane & 8);      // A rows (Q / P)
    const int aco2 = lane & 16;                  // A col byte add
    const int bro  = la7 + ((lane & 16) >> 1);   // B rows (K), + np*16
    const int bco2 = (lane & 8) * 2;             // B col byte add
    const int vro  = la7 + (lane & 8);           // V rows (key), + ks*16
    const int vco2 = lane & 16;                  // V col byte add, + np*32

    // Load Q tile
    for (int i = tid; i < 128 * 16; i += 256) {
        int r = i >> 4, c = (i & 15) * 8;
        *(uint4*)(q_s + r * QST + c) =
            *(const uint4*)(g_q + (size_t)(m0 + r) * HID + h * HD + c);
    }

    float mrow[2] = {-INFINITY, -INFINITY};
    float lrow[2] = {0.f, 0.f};
    float oacc[16][4];
    #pragma unroll
    for (int nt = 0; nt < 16; nt++)
        #pragma unroll
        for (int c = 0; c < 4; c++) oacc[nt][c] = 0.f;

    const __half* kcb = g_kc + (size_t)h * KCP * HD;
    const __half* vcb = g_vc + (size_t)h * KCP * HD;

    for (int kt = 0; kt < NKT; kt++) {
        __syncthreads();                 // kv_s free (covers q_s at kt=0)
        for (int i = tid; i < 128 * 16; i += 256) {
            int r = i >> 4, c = (i & 15) * 8;
            *(uint4*)(kv_s + r * QST + c) =
                *(const uint4*)(kcb + (size_t)(kt * 128 + r) * HD + c);
        }
        __syncthreads();

        // S = Q @ K^T  (16 q-rows x 128 keys per warp)
        float sacc[16][4];
        #pragma unroll
        for (int nt = 0; nt < 16; nt++)
            #pragma unroll
            for (int c = 0; c < 4; c++) sacc[nt][c] = 0.f;

        #pragma unroll
        for (int ks = 0; ks < 8; ks++) {
            const int kk2 = ks * 32;
            uint32_t a0, a1, a2, a3;
            ldsm4(a0, a1, a2, a3, qu + (uint32_t)(aro * (QST * 2) + kk2 + aco2));
            #pragma unroll
            for (int np = 0; np < 8; np++) {
                uint32_t r0, r1, r2, r3;
                ldsm4(r0, r1, r2, r3,
                      kvu + (uint32_t)((np * 16 + bro) * (QST * 2) + kk2 + bco2));
                mma_f16(sacc[2 * np],     a0, a1, a2, a3, r0, r1);
                mma_f16(sacc[2 * np + 1], a0, a1, a2, a3, r2, r3);
            }
        }

        if (kt == NKT - 1) {
            #pragma unroll
            for (int nt = 0; nt < 16; nt++) {
                int j = kt * 128 + nt * 8 + tg * 2;
                #pragma unroll
                for (int c = 0; c < 4; c++)
                    if (j + (c & 1) >= KC) sacc[nt][c] = -INFINITY;
            }
        }

        // online softmax (rows g, g+8)
        #pragma unroll
        for (int half = 0; half < 2; half++) {
            float mx = -INFINITY;
            #pragma unroll
            for (int nt = 0; nt < 16; nt++) {
                mx = fmaxf(mx, sacc[nt][2 * half]);
                mx = fmaxf(mx, sacc[nt][2 * half + 1]);
            }
            mx = fmaxf(mx, __shfl_xor_sync(0xffffffffu, mx, 1));
            mx = fmaxf(mx, __shfl_xor_sync(0xffffffffu, mx, 2));
            float mnew  = fmaxf(mrow[half], mx);
            float alpha = __expf(mrow[half] - mnew);
            mrow[half] = mnew;

            float rsum = 0.f;
            #pragma unroll
            for (int nt = 0; nt < 16; nt++) {
                float p0 = __expf(sacc[nt][2 * half]     - mnew);
                float p1 = __expf(sacc[nt][2 * half + 1] - mnew);
                rsum += p0 + p1;
                *(__half2*)(p_s + (rb + g + 8 * half) * QST + nt * 8 + tg * 2) =
                    __floats2half2_rn(p0, p1);
                oacc[nt][2 * half]     *= alpha;
                oacc[nt][2 * half + 1] *= alpha;
            }
            rsum += __shfl_xor_sync(0xffffffffu, rsum, 1);
            rsum += __shfl_xor_sync(0xffffffffu, rsum, 2);
            lrow[half] = lrow[half] * alpha + rsum;
        }

        __syncthreads();                 // done reading K
        for (int i = tid; i < 128 * 16; i += 256) {
            int r = i >> 4, c = (i & 15) * 8;
            *(uint4*)(kv_s + r * QST + c) =
                *(const uint4*)(vcb + (size_t)(kt * 128 + r) * HD + c);
        }
        __syncthreads();

        // O += P @ V   (A = P rows, k = key; B = V via trans-ldmatrix)
        #pragma unroll
        for (int ks = 0; ks < 8; ks++) {
            const int kk2 = ks * 32;
            uint32_t a0, a1, a2, a3;
            ldsm4(a0, a1, a2, a3, pu + (uint32_t)(aro * (QST * 2) + kk2 + aco2));
            #pragma unroll
            for (int np = 0; np < 8; np++) {
                uint32_t r0, r1, r2, r3;
                ldsm4t(r0, r1, r2, r3,
                       kvu + (uint32_t)((ks * 16 + vro) * (QST * 2) + np * 32 + vco2));
                mma_f16(oacc[2 * np],     a0, a1, a2, a3, r0, r1);
                mma_f16(oacc[2 * np + 1], a0, a1, a2, a3, r2, r3);
            }
        }
    }

    // write attention output (fp16)
    #pragma unroll
    for (int half = 0; half < 2; half++) {
        int r = m0 + rb + g + 8 * half;
        float inv_l = 1.f / lrow[half];
        #pragma unroll
        for (int nt = 0; nt < 16; nt++) {
            int c = h * HD + nt * 8 + tg * 2;
            *(__half2*)(g_ao + (size_t)r * HID + c) =
                __floats2half2_rn(oacc[nt][2 * half] * inv_l,
                                  oacc[nt][2 * half + 1] * inv_l);
        }
    }
}

// ---------------------------------------------------------------------------
extern "C" void kernel_launch(void* const* d_in, const int* in_sizes, int n_in,
                              void* d_out, int out_size)
{
    const float* X  = (const float*)d_in[0];
    const float* Wq = (const float*)d_in[1];
    const float* bq = (const float*)d_in[2];
    const float* Wk = (const float*)d_in[3];
    const float* bk = (const float*)d_in[4];
    const float* Wv = (const float*)d_in[5];
    const float* bv = (const float*)d_in[6];
    const float* Wo = (const float*)d_in[7];
    const float* bo = (const float*)d_in[8];
    float* out = (float*)d_out;

    __half *pq, *pk, *pv, *pao, *pxh, *pwh;
    cudaGetSymbolAddress((void**)&pq,  g_q);
    cudaGetSymbolAddress((void**)&pk,  g_k);
    cudaGetSymbolAddress((void**)&pv,  g_v);
    cudaGetSymbolAddress((void**)&pao, g_ao);
    cudaGetSymbolAddress((void**)&pxh, g_xh);
    cudaGetSymbolAddress((void**)&pwh, g_wh);

    cudaFuncSetAttribute(gemm_f16<0>, cudaFuncAttributeMaxDynamicSharedMemorySize, GSMEM);
    cudaFuncSetAttribute(gemm_f16<1>, cudaFuncAttributeMaxDynamicSharedMemorySize, GSMEM);
    cudaFuncSetAttribute(gemm_f16<2>, cudaFuncAttributeMaxDynamicSharedMemorySize, GSMEM);
    cudaFuncSetAttribute(gemm_f16<3>, cudaFuncAttributeMaxDynamicSharedMemorySize, GSMEM);
    cudaFuncSetAttribute(attn_kernel, cudaFuncAttributeMaxDynamicSharedMemorySize, ATT_SMEM_B);

    conv_w<<<dim3(HID * HID / 1024, 4), 256>>>(Wq, Wk, Wv, Wo);
    conv_x<<<SEQ * HID / 1024, 256>>>(X);
    theta_kernel<<<1, 64>>>();

    const size_t WS = (size_t)HID * HID;
    dim3 ggrid(HID / 128, SEQ / 128);
    gemm_f16<2><<<ggrid, 256, GSMEM>>>(pxh, pwh + WS,     bk, pk);
    gemm_f16<3><<<ggrid, 256, GSMEM>>>(pxh, pwh + 2 * WS, bv, pv);
    gemm_f16<1><<<ggrid, 256, GSMEM>>>(pxh, pwh,          bq, pq);

    gather_kv<<<HEADS * KCP * 16 / 256, 256>>>();

    attn_kernel<<<dim3(SEQ / 128, HEADS), 256, ATT_SMEM_B>>>();

    gemm_f16<0><<<ggrid, 256, GSMEM>>>(pao, pwh + 3 * WS, bo, out);
}

// round 9
// speedup vs baseline: 2.8499x; 1.0504x over previous
#include <cuda_runtime.h>
#include <cuda_fp16.h>
#include <math.h>
#include <stdint.h>

// ---------------------------------------------------------------------------
// MiniGPT4AttentionCam  (B=1, S=4096, HID=2048, 16 heads x 128)
// R9: fp16 mma.sync + ldmatrix + cp.async (sm_100 base ISA).
//     GEMMs: CTA 256x128, warp 64x64, BK=64, 3-stage  (LDSM/MMA 0.25)
//     Attention: double-buffered cp.async K/V pipeline, 2 syncs per tile.
// ---------------------------------------------------------------------------

#define SEQ    4096
#define HID    2048
#define HEADS  16
#define HD     128
#define SB     410
#define RSTART 3072
#define KC     1434
#define KCP    1536
#define NKT    12

// Scratch (fp16 everywhere)
__device__ __half g_q [(size_t)SEQ * HID];
__device__ __half g_k [(size_t)SEQ * HID];
__device__ __half g_v [(size_t)SEQ * HID];
__device__ __half g_ao[(size_t)SEQ * HID];
__device__ __half g_kc[(size_t)HEADS * KCP * HD];
__device__ __half g_vc[(size_t)HEADS * KCP * HD];
__device__ __half g_xh[(size_t)SEQ * HID];
__device__ __half g_wh[(size_t)4 * HID * HID];
__device__ float  g_theta[64];

// ---------------- helpers ----------------
__device__ __forceinline__ uint32_t s2u(const void* p) {
    uint32_t a;
    asm("{ .reg .u64 t; cvta.to.shared.u64 t, %1; cvt.u32.u64 %0, t; }"
        : "=r"(a) : "l"(p));
    return a;
}
__device__ __forceinline__ void cp16(uint32_t s, const void* g) {
    asm volatile("cp.async.ca.shared.global [%0], [%1], 16;\n" :: "r"(s), "l"(g));
}
__device__ __forceinline__ void cp_commit() {
    asm volatile("cp.async.commit_group;\n");
}
template<int N>
__device__ __forceinline__ void cp_wait() {
    asm volatile("cp.async.wait_group %0;\n" :: "n"(N));
}

#define SWZ128(o) ((o) ^ (((o) >> 3) & 0x70))

__device__ __forceinline__ void ldsm4(uint32_t& r0, uint32_t& r1, uint32_t& r2,
                                      uint32_t& r3, uint32_t addr) {
    asm volatile("ldmatrix.sync.aligned.m8n8.x4.shared.b16 {%0,%1,%2,%3}, [%4];"
        : "=r"(r0), "=r"(r1), "=r"(r2), "=r"(r3) : "r"(addr));
}
__device__ __forceinline__ void ldsm4t(uint32_t& r0, uint32_t& r1, uint32_t& r2,
                                       uint32_t& r3, uint32_t addr) {
    asm volatile("ldmatrix.sync.aligned.m8n8.x4.trans.shared.b16 {%0,%1,%2,%3}, [%4];"
        : "=r"(r0), "=r"(r1), "=r"(r2), "=r"(r3) : "r"(addr));
}
__device__ __forceinline__ void mma_f16(float c[4],
    uint32_t a0, uint32_t a1, uint32_t a2, uint32_t a3,
    uint32_t b0, uint32_t b1)
{
    asm volatile(
        "mma.sync.aligned.m16n8k16.row.col.f32.f16.f16.f32 "
        "{%0,%1,%2,%3}, {%4,%5,%6,%7}, {%8,%9}, {%0,%1,%2,%3};\n"
        : "+f"(c[0]), "+f"(c[1]), "+f"(c[2]), "+f"(c[3])
        : "r"(a0), "r"(a1), "r"(a2), "r"(a3), "r"(b0), "r"(b1));
}

// ---------------------------------------------------------------------------
// Pre-convert to fp16
// ---------------------------------------------------------------------------
__global__ void conv_w(const float* __restrict__ Wq, const float* __restrict__ Wk,
                       const float* __restrict__ Wv, const float* __restrict__ Wo)
{
    int a = blockIdx.y;
    const float* src = (a == 0) ? Wq : (a == 1) ? Wk : (a == 2) ? Wv : Wo;
    size_t i = ((size_t)blockIdx.x * blockDim.x + threadIdx.x) * 4;
    float4 v = *(const float4*)(src + i);
    __half* d = g_wh + (size_t)a * HID * HID + i;
    *(__half2*)(d)     = __floats2half2_rn(v.x, v.y);
    *(__half2*)(d + 2) = __floats2half2_rn(v.z, v.w);
}

__global__ void conv_x(const float* __restrict__ X)
{
    size_t i = ((size_t)blockIdx.x * blockDim.x + threadIdx.x) * 4;
    float4 v = *(const float4*)(X + i);
    *(__half2*)(g_xh + i)     = __floats2half2_rn(v.x, v.y);
    *(__half2*)(g_xh + i + 2) = __floats2half2_rn(v.z, v.w);
}

__global__ void theta_kernel() {
    int p = threadIdx.x;
    if (p < 64) g_theta[p] = (float)pow(10000.0, -(double)p / 64.0);
}

// ---------------------------------------------------------------------------
// fp16 GEMM: C[4096,2048] = A @ B^T + bias
// CTA 256x128, BK=64, 3-stage cp.async, 256 thr, 8 warps 4m x 2n (64x64 warp).
// MODE: 0=O(float out) 1=Q(rope+scale,fp16) 2=K(rope,fp16) 3=V(fp16)
// ---------------------------------------------------------------------------
#define GA_B     32768                 // A tile: 256 rows x 128 B
#define GB_B     16384                 // B tile: 128 rows x 128 B
#define GSTAGE_B (GA_B + GB_B)         // 49152
#define GSMEM    (3 * GSTAGE_B)        // 147456 B
#define NTILES   32                    // 2048 / 64

template<int MODE>
__global__ void __launch_bounds__(256, 1)
gemm_f16(const __half* __restrict__ A, const __half* __restrict__ B,
         const float* __restrict__ bias, void* __restrict__ Cout)
{
    extern __shared__ char smem[];
    const uint32_t su = s2u(smem);
    const int tid = threadIdx.x, w = tid >> 5, lane = tid & 31;
    const int g = lane >> 2, tg = lane & 3;
    const int wm = w & 3, wn = w >> 2;
    const int m0 = blockIdx.y * 256, n0 = blockIdx.x * 128;

    float acc[4][8][4];
    #pragma unroll
    for (int a = 0; a < 4; a++)
        #pragma unroll
        for (int b = 0; b < 8; b++)
            #pragma unroll
            for (int q = 0; q < 4; q++) acc[a][b][q] = 0.f;

    const int la7 = lane & 7;
    const int arow  = wm * 64 + la7 + (lane & 8);        // + mt*16
    const int acol2 = lane & 16;                         // byte add
    const int brow0 = wn * 64 + la7 + ((lane & 16) >> 1);// + np*16
    const int bcol2 = (lane & 8) * 2;

    const char* gA = (const char*)A;
    const char* gB = (const char*)B;

    auto FILL = [&](int st, int kt) {
        uint32_t sb = su + st * GSTAGE_B;
        #pragma unroll
        for (int i = 0; i < 8; i++) {            // A: 256 rows
            int idx = tid + i * 256;
            int m = idx >> 3, c = (idx & 7) << 4;
            uint32_t so = SWZ128((uint32_t)(m * 128 + c));
            cp16(sb + so, gA + (size_t)(m0 + m) * (HID * 2) + kt * 128 + c);
        }
        #pragma unroll
        for (int i = 0; i < 4; i++) {            // B: 128 rows
            int idx = tid + i * 256;
            int m = idx >> 3, c = (idx & 7) << 4;
            uint32_t so = SWZ128((uint32_t)(m * 128 + c));
            cp16(sb + GA_B + so, gB + (size_t)(n0 + m) * (HID * 2) + kt * 128 + c);
        }
        cp_commit();
    };

    FILL(0, 0);
    FILL(1, 1);
    cp_wait<1>();
    __syncthreads();

    int st = 0, ld = 2;
    for (int kt = 0; kt < NTILES; kt++) {
        uint32_t sA = su + st * GSTAGE_B;
        uint32_t sB = sA + GA_B;

        #pragma unroll
        for (int ks = 0; ks < 4; ks++) {
            const int kk2 = ks * 32;
            uint32_t a[4][4];
            #pragma unroll
            for (int mt = 0; mt < 4; mt++) {
                uint32_t off = SWZ128((uint32_t)((arow + mt * 16) * 128 + kk2 + acol2));
                ldsm4(a[mt][0], a[mt][1], a[mt][2], a[mt][3], sA + off);
            }
            uint32_t b[8][2];
            #pragma unroll
            for (int np = 0; np < 4; np++) {
                uint32_t off = SWZ128((uint32_t)((brow0 + np * 16) * 128 + kk2 + bcol2));
                uint32_t r0, r1, r2, r3;
                ldsm4(r0, r1, r2, r3, sB + off);
                b[2 * np][0] = r0; b[2 * np][1] = r1;
                b[2 * np + 1][0] = r2; b[2 * np + 1][1] = r3;
            }
            #pragma unroll
            for (int mt = 0; mt < 4; mt++)
                #pragma unroll
                for (int nt = 0; nt < 8; nt++)
                    mma_f16(acc[mt][nt], a[mt][0], a[mt][1], a[mt][2], a[mt][3],
                            b[nt][0], b[nt][1]);
        }

        if (kt + 2 < NTILES) {
            FILL(ld, kt + 2);
            ld = (ld == 2) ? 0 : ld + 1;
        } else {
            cp_commit();
        }
        cp_wait<1>();
        __syncthreads();
        st = (st == 2) ? 0 : st + 1;
    }

    // ---- epilogue ----
    if (MODE == 0) {
        float* C = (float*)Cout;
        #pragma unroll
        for (int mt = 0; mt < 4; mt++) {
            int r0 = m0 + wm * 64 + mt * 16 + g;
            #pragma unroll
            for (int nt = 0; nt < 8; nt++) {
                int c = n0 + wn * 64 + nt * 8 + tg * 2;
                float2 b2 = *(const float2*)(bias + c);
                *(float2*)(C + (size_t)r0 * HID + c) =
                    make_float2(acc[mt][nt][0] + b2.x, acc[mt][nt][1] + b2.y);
                *(float2*)(C + (size_t)(r0 + 8) * HID + c) =
                    make_float2(acc[mt][nt][2] + b2.x, acc[mt][nt][3] + b2.y);
            }
        }
    } else if (MODE == 3) {
        __half* C = (__half*)Cout;
        #pragma unroll
        for (int mt = 0; mt < 4; mt++) {
            int r0 = m0 + wm * 64 + mt * 16 + g;
            #pragma unroll
            for (int nt = 0; nt < 8; nt++) {
                int c = n0 + wn * 64 + nt * 8 + tg * 2;
                float2 b2 = *(const float2*)(bias + c);
                *(__half2*)(C + (size_t)r0 * HID + c) =
                    __floats2half2_rn(acc[mt][nt][0] + b2.x, acc[mt][nt][1] + b2.y);
                *(__half2*)(C + (size_t)(r0 + 8) * HID + c) =
                    __floats2half2_rn(acc[mt][nt][2] + b2.x, acc[mt][nt][3] + b2.y);
            }
        }
    } else {
        __half* C = (__half*)Cout;
        const float SC = (MODE == 1) ? 0.08838834764831845f : 1.0f;
        #pragma unroll
        for (int mt = 0; mt < 4; mt++) {
            int r0 = m0 + wm * 64 + mt * 16 + g;
            #pragma unroll
            for (int nt = 0; nt < 8; nt++) {
                int c = n0 + wn * 64 + nt * 8 + tg * 2;
                int hb = c & ~127;
                int p  = (c & 127) >> 1;
                float th = g_theta[p];
                float y1a = acc[mt][nt][0] + bias[c];
                float y2a = acc[mt][nt][1] + bias[c + 1];
                float y1b = acc[mt][nt][2] + bias[c];
                float y2b = acc[mt][nt][3] + bias[c + 1];
                float sn, cs;
                sincosf((float)r0 * th, &sn, &cs);
                C[(size_t)r0 * HID + hb + p]      = __float2half_rn((y1a * cs - y2a * sn) * SC);
                C[(size_t)r0 * HID + hb + p + 64] = __float2half_rn((y1a * sn + y2a * cs) * SC);
                sincosf((float)(r0 + 8) * th, &sn, &cs);
                C[(size_t)(r0 + 8) * HID + hb + p]      = __float2half_rn((y1b * cs - y2b * sn) * SC);
                C[(size_t)(r0 + 8) * HID + hb + p + 64] = __float2half_rn((y1b * sn + y2b * cs) * SC);
            }
        }
    }
}

// ---------------------------------------------------------------------------
// Gather compact K/V (fp16, 16B chunks)
// ---------------------------------------------------------------------------
__global__ void gather_kv() {
    int idx = blockIdx.x * blockDim.x + threadIdx.x;
    if (idx >= HEADS * KCP * 16) return;
    int c8  = (idx & 15) * 8;
    int row = idx >> 4;
    int h = row / KCP, j = row % KCP;
    uint4 vk = make_uint4(0, 0, 0, 0);
    uint4 vv = vk;
    if (j < KC) {
        int s = (j < SB) ? j : (RSTART + (j - SB));
        size_t off = (size_t)s * HID + h * HD + c8;
        vk = *(const uint4*)(g_k + off);
        vv = *(const uint4*)(g_v + off);
    }
    size_t doff = (size_t)row * HD + c8;
    *(uint4*)(g_kc + doff) = vk;
    *(uint4*)(g_vc + doff) = vv;
}

// ---------------------------------------------------------------------------
// Flash attention over compact keys, double-buffered cp.async K/V pipeline.
// Buffers: q | k0 | k1 | v0 | v1 | p   (each 128 x 136 halves)
// ---------------------------------------------------------------------------
#define QST 136
#define ABUF (128 * QST)
#define ATT_SMEM_B (6 * ABUF * 2)        // 208896 B

__global__ __launch_bounds__(256, 1)
void attn_kernel()
{
    extern __shared__ __half smem_att[];
    __half* q_s = smem_att;
    __half* p_s = smem_att + 5 * ABUF;
    const uint32_t qu = s2u(q_s);
    const uint32_t pu = s2u(p_s);
    const uint32_t ku0 = s2u(smem_att + 1 * ABUF);
    const uint32_t ku1 = s2u(smem_att + 2 * ABUF);
    const uint32_t vu0 = s2u(smem_att + 3 * ABUF);
    const uint32_t vu1 = s2u(smem_att + 4 * ABUF);

    const int h = blockIdx.y, m0 = blockIdx.x * 128;
    const int tid = threadIdx.x, w = tid >> 5, lane = tid & 31;
    const int g = lane >> 2, tg = lane & 3;
    const int rb = w * 16;
    const int la7 = lane & 7;

    const int aro  = rb + la7 + (lane & 8);
    const int aco2 = lane & 16;
    const int bro  = la7 + ((lane & 16) >> 1);
    const int bco2 = (lane & 8) * 2;
    const int vro  = la7 + (lane & 8);
    const int vco2 = lane & 16;

    const __half* kcb = g_kc + (size_t)h * KCP * HD;
    const __half* vcb = g_vc + (size_t)h * KCP * HD;

    auto FILL_KV = [&](uint32_t kb, uint32_t vb, int kt) {
        #pragma unroll
        for (int i = 0; i < 8; i++) {
            int idx = tid + i * 256;
            int r = idx >> 4;
            int cby = (idx & 15) * 16;
            uint32_t so = (uint32_t)(r * (QST * 2) + cby);
            const char* gk = (const char*)(kcb + (size_t)(kt * 128 + r) * HD) + cby;
            const char* gv = (const char*)(vcb + (size_t)(kt * 128 + r) * HD) + cby;
            cp16(kb + so, gk);
            cp16(vb + so, gv);
        }
        cp_commit();
    };

    // Load Q tile (plain stores; visible after first __syncthreads)
    for (int i = tid; i < 128 * 16; i += 256) {
        int r = i >> 4, c = (i & 15) * 8;
        *(uint4*)(q_s + r * QST + c) =
            *(const uint4*)(g_q + (size_t)(m0 + r) * HID + h * HD + c);
    }

    FILL_KV(ku0, vu0, 0);
    FILL_KV(ku1, vu1, 1);

    float mrow[2] = {-INFINITY, -INFINITY};
    float lrow[2] = {0.f, 0.f};
    float oacc[16][4];
    #pragma unroll
    for (int nt = 0; nt < 16; nt++)
        #pragma unroll
        for (int c = 0; c < 4; c++) oacc[nt][c] = 0.f;

    for (int kt = 0; kt < NKT; kt++) {
        cp_wait<1>();                    // group kt complete (in-order)
        __syncthreads();                 // data visible to all warps
        const uint32_t kbu = (kt & 1) ? ku1 : ku0;
        const uint32_t vbu = (kt & 1) ? vu1 : vu0;

        // S = Q @ K^T
        float sacc[16][4];
        #pragma unroll
        for (int nt = 0; nt < 16; nt++)
            #pragma unroll
            for (int c = 0; c < 4; c++) sacc[nt][c] = 0.f;

        #pragma unroll
        for (int ks = 0; ks < 8; ks++) {
            const int kk2 = ks * 32;
            uint32_t a0, a1, a2, a3;
            ldsm4(a0, a1, a2, a3, qu + (uint32_t)(aro * (QST * 2) + kk2 + aco2));
            #pragma unroll
            for (int np = 0; np < 8; np++) {
                uint32_t r0, r1, r2, r3;
                ldsm4(r0, r1, r2, r3,
                      kbu + (uint32_t)((np * 16 + bro) * (QST * 2) + kk2 + bco2));
                mma_f16(sacc[2 * np],     a0, a1, a2, a3, r0, r1);
                mma_f16(sacc[2 * np + 1], a0, a1, a2, a3, r2, r3);
            }
        }

        if (kt == NKT - 1) {
            #pragma unroll
            for (int nt = 0; nt < 16; nt++) {
                int j = kt * 128 + nt * 8 + tg * 2;
                #pragma unroll
                for (int c = 0; c < 4; c++)
                    if (j + (c & 1) >= KC) sacc[nt][c] = -INFINITY;
            }
        }

        // online softmax (rows g, g+8); P staged warp-locally
        #pragma unroll
        for (int half = 0; half < 2; half++) {
            float mx = -INFINITY;
            #pragma unroll
            for (int nt = 0; nt < 16; nt++) {
                mx = fmaxf(mx, sacc[nt][2 * half]);
                mx = fmaxf(mx, sacc[nt][2 * half + 1]);
            }
            mx = fmaxf(mx, __shfl_xor_sync(0xffffffffu, mx, 1));
            mx = fmaxf(mx, __shfl_xor_sync(0xffffffffu, mx, 2));
            float mnew  = fmaxf(mrow[half], mx);
            float alpha = __expf(mrow[half] - mnew);
            mrow[half] = mnew;

            float rsum = 0.f;
            #pragma unroll
            for (int nt = 0; nt < 16; nt++) {
                float p0 = __expf(sacc[nt][2 * half]     - mnew);
                float p1 = __expf(sacc[nt][2 * half + 1] - mnew);
                rsum += p0 + p1;
                *(__half2*)(p_s + (rb + g + 8 * half) * QST + nt * 8 + tg * 2) =
                    __floats2half2_rn(p0, p1);
                oacc[nt][2 * half]     *= alpha;
                oacc[nt][2 * half + 1] *= alpha;
            }
            rsum += __shfl_xor_sync(0xffffffffu, rsum, 1);
            rsum += __shfl_xor_sync(0xffffffffu, rsum, 2);
            lrow[half] = lrow[half] * alpha + rsum;
        }
        __syncwarp();                    // P visible within warp for ldmatrix

        // O += P @ V   (V via trans-ldmatrix)
        #pragma unroll
        for (int ks = 0; ks < 8; ks++) {
            const int kk2 = ks * 32;
            uint32_t a0, a1, a2, a3;
            ldsm4(a0, a1, a2, a3, pu + (uint32_t)(aro * (QST * 2) + kk2 + aco2));
            #pragma unroll
            for (int np = 0; np < 8; np++) {
                uint32_t r0, r1, r2, r3;
                ldsm4t(r0, r1, r2, r3,
                       vbu + (uint32_t)((ks * 16 + vro) * (QST * 2) + np * 32 + vco2));
                mma_f16(oacc[2 * np],     a0, a1, a2, a3, r0, r1);
                mma_f16(oacc[2 * np + 1], a0, a1, a2, a3, r2, r3);
            }
        }

        __syncthreads();                 // all reads of buf kt&1 complete
        if (kt + 2 < NKT) {
            FILL_KV((kt & 1) ? ku1 : ku0, (kt & 1) ? vu1 : vu0, kt + 2);
        } else {
            cp_commit();                 // keep wait-group ledger aligned
        }
    }

    // write attention output (fp16)
    #pragma unroll
    for (int half = 0; half < 2; half++) {
        int r = m0 + rb + g + 8 * half;
        float inv_l = 1.f / lrow[half];
        #pragma unroll
        for (int nt = 0; nt < 16; nt++) {
            int c = h * HD + nt * 8 + tg * 2;
            *(__half2*)(g_ao + (size_t)r * HID + c) =
                __floats2half2_rn(oacc[nt][2 * half] * inv_l,
                                  oacc[nt][2 * half + 1] * inv_l);
        }
    }
}

// ---------------------------------------------------------------------------
extern "C" void kernel_launch(void* const* d_in, const int* in_sizes, int n_in,
                              void* d_out, int out_size)
{
    const float* X  = (const float*)d_in[0];
    const float* Wq = (const float*)d_in[1];
    const float* bq = (const float*)d_in[2];
    const float* Wk = (const float*)d_in[3];
    const float* bk = (const float*)d_in[4];
    const float* Wv = (const float*)d_in[5];
    const float* bv = (const float*)d_in[6];
    const float* Wo = (const float*)d_in[7];
    const float* bo = (const float*)d_in[8];
    float* out = (float*)d_out;

    __half *pq, *pk, *pv, *pao, *pxh, *pwh;
    cudaGetSymbolAddress((void**)&pq,  g_q);
    cudaGetSymbolAddress((void**)&pk,  g_k);
    cudaGetSymbolAddress((void**)&pv,  g_v);
    cudaGetSymbolAddress((void**)&pao, g_ao);
    cudaGetSymbolAddress((void**)&pxh, g_xh);
    cudaGetSymbolAddress((void**)&pwh, g_wh);

    cudaFuncSetAttribute(gemm_f16<0>, cudaFuncAttributeMaxDynamicSharedMemorySize, GSMEM);
    cudaFuncSetAttribute(gemm_f16<1>, cudaFuncAttributeMaxDynamicSharedMemorySize, GSMEM);
    cudaFuncSetAttribute(gemm_f16<2>, cudaFuncAttributeMaxDynamicSharedMemorySize, GSMEM);
    cudaFuncSetAttribute(gemm_f16<3>, cudaFuncAttributeMaxDynamicSharedMemorySize, GSMEM);
    cudaFuncSetAttribute(attn_kernel, cudaFuncAttributeMaxDynamicSharedMemorySize, ATT_SMEM_B);

    conv_w<<<dim3(HID * HID / 1024, 4), 256>>>(Wq, Wk, Wv, Wo);
    conv_x<<<SEQ * HID / 1024, 256>>>(X);
    theta_kernel<<<1, 64>>>();

    const size_t WS = (size_t)HID * HID;
    dim3 ggrid(HID / 128, SEQ / 256);
    gemm_f16<2><<<ggrid, 256, GSMEM>>>(pxh, pwh + WS,     bk, pk);
    gemm_f16<3><<<ggrid, 256, GSMEM>>>(pxh, pwh + 2 * WS, bv, pv);
    gemm_f16<1><<<ggrid, 256, GSMEM>>>(pxh, pwh,          bq, pq);

    gather_kv<<<HEADS * KCP * 16 / 256, 256>>>();

    attn_kernel<<<dim3(SEQ / 128, HEADS), 256, ATT_SMEM_B>>>();

    gemm_f16<0><<<ggrid, 256, GSMEM>>>(pao, pwh + 3 * WS, bo, out);
}